// round 1
// baseline (speedup 1.0000x reference)
#include <cuda_runtime.h>
#include <math.h>

#define BB 4
#define NN 2048
#define KNN 48
#define NRBF 16
#define NPE 16
#define EDGE_C 128
#define PE_IN 66
#define MAXREL 32

// scratch (no cudaMalloc allowed)
__device__ float g_X[BB * NN * 3];          // gathered, masked token coords
__device__ float g_PW[PE_IN * EDGE_C];      // (pe_w[d]+pe_b) @ edge_w[0:16]  per d

// ---------------------------------------------------------------------------
// Kernel 1: gather center-atom coords, apply mask
// ---------------------------------------------------------------------------
__global__ void gather_kernel(const float* __restrict__ coords,
                              const float* __restrict__ mask,
                              const int* __restrict__ t2c) {
    int t = blockIdx.x * blockDim.x + threadIdx.x;   // b*N + n
    if (t >= BB * NN) return;
    int b = t / NN;
    int a = t2c[t];
    float m = mask[t];
    const float* src = coords + ((size_t)b * NN + a) * 3;
    g_X[t * 3 + 0] = src[0] * m;
    g_X[t * 3 + 1] = src[1] * m;
    g_X[t * 3 + 2] = src[2] * m;
}

// ---------------------------------------------------------------------------
// Kernel 2: precompute positional table PW[d][c] = sum_p (pe_w[d,p]+pe_b[p])*edge_w[p,c]
// ---------------------------------------------------------------------------
__global__ void pw_kernel(const float* __restrict__ pe_w,
                          const float* __restrict__ pe_b,
                          const float* __restrict__ edge_w) {
    int d = blockIdx.x;      // 0..65
    int c = threadIdx.x;     // 0..127
    float acc = 0.f;
#pragma unroll
    for (int p = 0; p < NPE; p++)
        acc += (pe_w[d * NPE + p] + pe_b[p]) * edge_w[p * EDGE_C + c];
    g_PW[d * EDGE_C + c] = acc;
}

// ---------------------------------------------------------------------------
// Kernel 3: per-row KNN (bitonic full sort of 64-bit keys) + fused feature
//           embed + layernorm epilogue.
// One block (256 threads) per row (b,i).
// ---------------------------------------------------------------------------
__global__ __launch_bounds__(256, 1)
void tokfeat_kernel(const float* __restrict__ mask,
                    const float* __restrict__ bonds,
                    const float* __restrict__ edge_w,
                    const float* __restrict__ ln_g,
                    const float* __restrict__ ln_b,
                    const int*   __restrict__ resi,
                    const int*   __restrict__ lig,
                    float* __restrict__ outE,
                    float* __restrict__ outIdx,
                    float* __restrict__ outD) {
    const int row = blockIdx.x;          // b*N + i
    const int b   = row / NN;
    const int i   = row - b * NN;
    const int tid = threadIdx.x;
    const int lane = tid & 31;
    const int wid  = tid >> 5;

    // union region: phase 1 coords (24KB) then phase 2/3 sort keys (16KB)
    __shared__ __align__(16) char ubuf[NN * 3 * sizeof(float)];
    float* xs = (float*)ubuf;
    unsigned long long* keys = (unsigned long long*)ubuf;

    __shared__ float sW2[NRBF * EDGE_C];   // rbf weight rows (8KB)
    __shared__ float sW3[EDGE_C];          // bond weight row
    __shared__ float sLg[EDGE_C];
    __shared__ float sLb[EDGE_C];
    __shared__ float sRed[8];
    __shared__ float sD[KNN];
    __shared__ float sTb[KNN];
    __shared__ int   sDc[KNN];

    // ---- load coords of this batch into shared ----
    const float* Xb = g_X + (size_t)b * NN * 3;
    for (int idx = tid; idx < NN * 3; idx += 256) xs[idx] = Xb[idx];
    __syncthreads();

    const float xi0 = xs[i * 3 + 0];
    const float xi1 = xs[i * 3 + 1];
    const float xi2 = xs[i * 3 + 2];
    const float mi  = mask[row];

    // ---- distances (8 per thread, strided) ----
    float dloc[8], m2loc[8];
    float vmax = 0.f;
#pragma unroll
    for (int s = 0; s < 8; s++) {
        int j = tid + s * 256;
        float dx = xi0 - xs[j * 3 + 0];
        float dy = xi1 - xs[j * 3 + 1];
        float dz = xi2 - xs[j * 3 + 2];
        float mj = mask[b * NN + j];
        float m2 = mi * mj;
        float D  = m2 * sqrtf(dx * dx + dy * dy + dz * dz + 1e-6f);
        dloc[s] = D; m2loc[s] = m2;
        vmax = fmaxf(vmax, D);
    }
    // block max reduce
#pragma unroll
    for (int o = 16; o; o >>= 1) vmax = fmaxf(vmax, __shfl_xor_sync(0xffffffffu, vmax, o));
    if (lane == 0) sRed[wid] = vmax;
    __syncthreads();   // also guarantees all xs reads done before key overwrite
    float Dmax = sRed[0];
#pragma unroll
    for (int r = 1; r < 8; r++) Dmax = fmaxf(Dmax, sRed[r]);

    // ---- build sort keys: (f32bits(D_adjust) << 32) | j  (asc == JAX top_k order) ----
#pragma unroll
    for (int s = 0; s < 8; s++) {
        int j = tid + s * 256;
        float Dadj = dloc[s] + (1.f - m2loc[s]) * Dmax;
        unsigned int bits = __float_as_uint(Dadj);
        keys[j] = ((unsigned long long)bits << 32) | (unsigned int)j;
    }
    __syncthreads();

    // ---- bitonic full sort ascending (2048 u64 keys) ----
    for (int k = 2; k <= NN; k <<= 1) {
        for (int j = k >> 1; j > 0; j >>= 1) {
            for (int t = tid; t < NN; t += 256) {
                int ixj = t ^ j;
                if (ixj > t) {
                    bool up = ((t & k) == 0);
                    unsigned long long a = keys[t];
                    unsigned long long c = keys[ixj];
                    if ((a > c) == up) { keys[t] = c; keys[ixj] = a; }
                }
            }
            __syncthreads();
        }
    }

    // ---- top-K scalars + idx/D outputs ----
    if (tid < KNN) {
        unsigned long long key = keys[tid];
        int   j = (int)(key & 0xffffffffu);
        float D = __uint_as_float((unsigned int)(key >> 32));
        sD[tid] = D;
        int off = resi[row] - resi[b * NN + j];
        int dc = off + MAXREL;
        dc = dc < 0 ? 0 : (dc > 2 * MAXREL ? 2 * MAXREL : dc);
        sDc[tid] = dc;  // chain labels all zero -> E_chains==1 always
        float tb = bonds[(size_t)row * NN + j];
        sTb[tid] = (lig[row] | lig[b * NN + j]) ? tb : 0.f;
        outIdx[(size_t)row * KNN + tid] = (float)j;
        outD  [(size_t)row * KNN + tid] = D;
    }
    // ---- stage weights ----
    for (int idx = tid; idx < NRBF * EDGE_C; idx += 256)
        sW2[idx] = edge_w[NPE * EDGE_C + idx];
    for (int idx = tid; idx < EDGE_C; idx += 256) {
        sW3[idx] = edge_w[(NPE + NRBF) * EDGE_C + idx];
        sLg[idx] = ln_g[idx];
        sLb[idx] = ln_b[idx];
    }
    __syncthreads();

    // ---- feature embed + layernorm: warp w handles edges w, w+8, ... ----
    for (int k = wid; k < KNN; k += 8) {
        float D  = sD[k];
        float tb = sTb[k];
        int   dc = sDc[k];
        // lane r (r = lane&15) computes rbf_r; broadcast via shfl in MAC loop
        int   r0 = lane & 15;
        float mu_r = 2.f + (20.f / 15.f) * (float)r0;
        float tt = (D - mu_r) * (1.f / 1.25f);
        float myrbf = expf(-tt * tt);

        const float* pw = g_PW + dc * EDGE_C;
        float acc[4];
#pragma unroll
        for (int q = 0; q < 4; q++) {
            int c = lane + q * 32;
            acc[q] = pw[c] + tb * sW3[c];
        }
#pragma unroll
        for (int r = 0; r < NRBF; r++) {
            float rb = __shfl_sync(0xffffffffu, myrbf, r);
#pragma unroll
            for (int q = 0; q < 4; q++)
                acc[q] += rb * sW2[r * EDGE_C + lane + q * 32];
        }
        // layernorm (two-pass: mean, then centered var)
        float s1 = 0.f;
#pragma unroll
        for (int q = 0; q < 4; q++) s1 += acc[q];
#pragma unroll
        for (int o = 16; o; o >>= 1) s1 += __shfl_xor_sync(0xffffffffu, s1, o);
        float mean = s1 * (1.f / 128.f);
        float s2 = 0.f;
#pragma unroll
        for (int q = 0; q < 4; q++) { float d = acc[q] - mean; s2 += d * d; }
#pragma unroll
        for (int o = 16; o; o >>= 1) s2 += __shfl_xor_sync(0xffffffffu, s2, o);
        float rstd = rsqrtf(s2 * (1.f / 128.f) + 1e-5f);

        size_t base = ((size_t)row * KNN + k) * EDGE_C;
#pragma unroll
        for (int q = 0; q < 4; q++) {
            int c = lane + q * 32;
            outE[base + c] = (acc[q] - mean) * rstd * sLg[c] + sLb[c];
        }
    }
}

// ---------------------------------------------------------------------------
extern "C" void kernel_launch(void* const* d_in, const int* in_sizes, int n_in,
                              void* d_out, int out_size) {
    const float* coords = (const float*)d_in[0];
    const float* mask   = (const float*)d_in[1];
    const float* bonds  = (const float*)d_in[2];
    const float* pe_w   = (const float*)d_in[3];
    const float* pe_b   = (const float*)d_in[4];
    const float* edge_w = (const float*)d_in[5];
    const float* ln_g   = (const float*)d_in[6];
    const float* ln_b   = (const float*)d_in[7];
    const int*   t2c    = (const int*)d_in[8];
    const int*   resi   = (const int*)d_in[9];
    // d_in[10] = asym_id (unused: chain labels forced to zero in reference)
    const int*   lig    = (const int*)d_in[11];

    float* out    = (float*)d_out;
    float* outE   = out;                                        // B*N*K*128
    float* outIdx = out + (size_t)BB * NN * KNN * EDGE_C;       // B*N*K
    float* outD   = outIdx + (size_t)BB * NN * KNN;             // B*N*K

    gather_kernel<<<(BB * NN + 255) / 256, 256>>>(coords, mask, t2c);
    pw_kernel<<<PE_IN, EDGE_C>>>(pe_w, pe_b, edge_w);
    tokfeat_kernel<<<BB * NN, 256>>>(mask, bonds, edge_w, ln_g, ln_b,
                                     resi, lig, outE, outIdx, outD);
}

// round 2
// speedup vs baseline: 4.1776x; 4.1776x over previous
#include <cuda_runtime.h>
#include <math.h>

#define BB 4
#define NN 2048
#define KNN 48
#define NRBF 16
#define NPE 16
#define EDGE_C 128
#define PE_IN 66
#define MAXREL 32

// scratch (no cudaMalloc allowed)
__device__ float4 g_X4[BB * NN];            // xyz = masked coords, w = mask
__device__ float  g_PW[PE_IN * EDGE_C];     // (pe_w[d]+pe_b) @ edge_w[0:16]

// ---------------------------------------------------------------------------
// Kernel 1: gather center-atom coords, apply mask, pack mask into .w
// ---------------------------------------------------------------------------
__global__ void gather_kernel(const float* __restrict__ coords,
                              const float* __restrict__ mask,
                              const int* __restrict__ t2c) {
    int t = blockIdx.x * blockDim.x + threadIdx.x;   // b*N + n
    if (t >= BB * NN) return;
    int b = t / NN;
    int a = t2c[t];
    float m = mask[t];
    const float* src = coords + ((size_t)b * NN + a) * 3;
    g_X4[t] = make_float4(src[0] * m, src[1] * m, src[2] * m, m);
}

// ---------------------------------------------------------------------------
// Kernel 2: positional table PW[d][c] = sum_p (pe_w[d,p]+pe_b[p])*edge_w[p,c]
// ---------------------------------------------------------------------------
__global__ void pw_kernel(const float* __restrict__ pe_w,
                          const float* __restrict__ pe_b,
                          const float* __restrict__ edge_w) {
    int d = blockIdx.x;      // 0..65
    int c = threadIdx.x;     // 0..127
    float acc = 0.f;
#pragma unroll
    for (int p = 0; p < NPE; p++)
        acc += (pe_w[d * NPE + p] + pe_b[p]) * edge_w[p * EDGE_C + c];
    g_PW[d * EDGE_C + c] = acc;
}

// ---------------------------------------------------------------------------
// Kernel 3: per-row exact KNN via 64-bit radix select + fused embed+LN.
// One block (256 threads) per row (b,i). Keys stay in registers.
// ---------------------------------------------------------------------------
__global__ __launch_bounds__(256)
void tokfeat_kernel(const float* __restrict__ bonds,
                    const float* __restrict__ edge_w,
                    const float* __restrict__ ln_g,
                    const float* __restrict__ ln_b,
                    const int*   __restrict__ resi,
                    const int*   __restrict__ lig,
                    float* __restrict__ outE,
                    float* __restrict__ outIdx,
                    float* __restrict__ outD) {
    const int row  = blockIdx.x;          // b*N + i
    const int b    = row / NN;
    const int i    = row - b * NN;
    const int tid  = threadIdx.x;
    const int lane = tid & 31;
    const int wid  = tid >> 5;

    __shared__ float sW2[NRBF * EDGE_C];   // rbf weight rows (8KB)
    __shared__ float sW3[EDGE_C];
    __shared__ float sLg[EDGE_C];
    __shared__ float sLb[EDGE_C];
    __shared__ float sRed[8];
    __shared__ int   sHist[256];
    __shared__ int   sWs[8];
    __shared__ int   sSelDig, sBelow, sCnt, sNum;
    __shared__ unsigned long long sKth;
    __shared__ unsigned long long sCand[KNN];
    __shared__ float sD[KNN];
    __shared__ float sTb[KNN];
    __shared__ int   sDc[KNN];

    // ---- stage weights early (overlaps with compute below) ----
    for (int idx = tid; idx < NRBF * EDGE_C; idx += 256)
        sW2[idx] = edge_w[NPE * EDGE_C + idx];
    if (tid < EDGE_C) {
        sW3[tid] = edge_w[(NPE + NRBF) * EDGE_C + tid];
        sLg[tid] = ln_g[tid];
        sLb[tid] = ln_b[tid];
    }

    // ---- distances: 8 neighbors per thread, from L2-resident float4 ----
    const float4* Xb = g_X4 + (size_t)b * NN;
    const float4 xi = Xb[i];

    float dloc[8], m2loc[8];
    float vmax = 0.f;
#pragma unroll
    for (int s = 0; s < 8; s++) {
        int j = tid + s * 256;
        float4 xj = Xb[j];
        float dx = xi.x - xj.x;
        float dy = xi.y - xj.y;
        float dz = xi.z - xj.z;
        float m2 = xi.w * xj.w;
        float D  = m2 * sqrtf(dx * dx + dy * dy + dz * dz + 1e-6f);
        dloc[s] = D; m2loc[s] = m2;
        vmax = fmaxf(vmax, D);
    }
#pragma unroll
    for (int o = 16; o; o >>= 1) vmax = fmaxf(vmax, __shfl_xor_sync(0xffffffffu, vmax, o));
    if (lane == 0) sRed[wid] = vmax;
    __syncthreads();
    float Dmax = sRed[0];
#pragma unroll
    for (int r = 1; r < 8; r++) Dmax = fmaxf(Dmax, sRed[r]);

    // ---- keys: (f32bits(D_adjust) << 32) | j  (asc == JAX top_k order) ----
    unsigned long long keys[8];
#pragma unroll
    for (int s = 0; s < 8; s++) {
        int j = tid + s * 256;
        float Dadj = dloc[s] + (1.f - m2loc[s]) * Dmax;
        keys[s] = ((unsigned long long)__float_as_uint(Dadj) << 32) | (unsigned int)j;
    }

    // ---- radix select: find the KNN-th smallest key exactly ----
    unsigned long long pref = 0;
    int krank = KNN;
    bool resolved = false;
    for (int shift = 56; shift >= 0; shift -= 8) {
        sHist[tid] = 0;
        __syncthreads();
        unsigned long long hm = (shift == 56) ? 0ULL : (~0ULL << (shift + 8));
#pragma unroll
        for (int s = 0; s < 8; s++) {
            unsigned long long key = keys[s];
            if ((key & hm) == pref)
                atomicAdd(&sHist[(int)((key >> shift) & 255)], 1);
        }
        __syncthreads();
        int v = sHist[tid];
        int sc = v;
#pragma unroll
        for (int o = 1; o < 32; o <<= 1) {
            int n = __shfl_up_sync(0xffffffffu, sc, o);
            if (lane >= o) sc += n;
        }
        if (lane == 31) sWs[wid] = sc;
        __syncthreads();
        if (wid == 0) {
            int wv = (lane < 8) ? sWs[lane] : 0;
#pragma unroll
            for (int o = 1; o < 8; o <<= 1) {
                int n = __shfl_up_sync(0xffffffffu, wv, o);
                if (lane >= o) wv += n;
            }
            if (lane < 8) sWs[lane] = wv;
        }
        __syncthreads();
        int cum = sc + (wid ? sWs[wid - 1] : 0);   // inclusive cumsum over bins
        if (cum >= krank && cum - v < krank) { sSelDig = tid; sBelow = cum - v; sCnt = v; }
        __syncthreads();
        pref |= ((unsigned long long)sSelDig << shift);
        krank -= sBelow;
        if (sCnt == 1) {
            unsigned long long hm2 = (shift == 0) ? ~0ULL : (~0ULL << shift);
#pragma unroll
            for (int s = 0; s < 8; s++)
                if ((keys[s] & hm2) == pref) sKth = keys[s];
            resolved = true;
        }
        __syncthreads();
        if (resolved) break;
    }
    unsigned long long kth = resolved ? sKth : pref;

    // ---- compact the exactly-48 keys <= kth (keys unique) ----
    if (tid == 0) sNum = 0;
    __syncthreads();
#pragma unroll
    for (int s = 0; s < 8; s++) {
        if (keys[s] <= kth) {
            int p = atomicAdd(&sNum, 1);
            sCand[p] = keys[s];
        }
    }
    __syncthreads();

    // ---- rank by counting (48x48), emit idx/D + per-edge scalars ----
    if (tid < KNN) {
        unsigned long long kk = sCand[tid];
        int rank = 0;
#pragma unroll 4
        for (int m = 0; m < KNN; m++) rank += (sCand[m] < kk);
        int   j = (int)(kk & 0xffffffffu);
        float D = __uint_as_float((unsigned int)(kk >> 32));
        sD[rank] = D;
        int off = resi[row] - resi[b * NN + j];
        int dc = off + MAXREL;
        dc = dc < 0 ? 0 : (dc > 2 * MAXREL ? 2 * MAXREL : dc);
        sDc[rank] = dc;   // chain labels all zero -> E_chains==1 always
        float tb = bonds[(size_t)row * NN + j];
        sTb[rank] = (lig[row] | lig[b * NN + j]) ? tb : 0.f;
        outIdx[(size_t)row * KNN + rank] = (float)j;
        outD  [(size_t)row * KNN + rank] = D;
    }
    __syncthreads();

    // ---- feature embed + layernorm: warp w handles edges w, w+8, ... ----
    for (int e = wid; e < KNN; e += 8) {
        float D  = sD[e];
        float tb = sTb[e];
        int   dc = sDc[e];
        int   r0 = lane & 15;
        float mu_r = 2.f + (20.f / 15.f) * (float)r0;
        float tt = (D - mu_r) * (1.f / 1.25f);
        float myrbf = expf(-tt * tt);

        const float* pw = g_PW + dc * EDGE_C;
        float acc[4];
#pragma unroll
        for (int q = 0; q < 4; q++) {
            int c = lane + q * 32;
            acc[q] = pw[c] + tb * sW3[c];
        }
#pragma unroll
        for (int r = 0; r < NRBF; r++) {
            float rb = __shfl_sync(0xffffffffu, myrbf, r);
#pragma unroll
            for (int q = 0; q < 4; q++)
                acc[q] += rb * sW2[r * EDGE_C + lane + q * 32];
        }
        float s1 = 0.f;
#pragma unroll
        for (int q = 0; q < 4; q++) s1 += acc[q];
#pragma unroll
        for (int o = 16; o; o >>= 1) s1 += __shfl_xor_sync(0xffffffffu, s1, o);
        float mean = s1 * (1.f / 128.f);
        float s2 = 0.f;
#pragma unroll
        for (int q = 0; q < 4; q++) { float d = acc[q] - mean; s2 += d * d; }
#pragma unroll
        for (int o = 16; o; o >>= 1) s2 += __shfl_xor_sync(0xffffffffu, s2, o);
        float rstd = rsqrtf(s2 * (1.f / 128.f) + 1e-5f);

        size_t base = ((size_t)row * KNN + e) * EDGE_C;
#pragma unroll
        for (int q = 0; q < 4; q++) {
            int c = lane + q * 32;
            outE[base + c] = (acc[q] - mean) * rstd * sLg[c] + sLb[c];
        }
    }
}

// ---------------------------------------------------------------------------
extern "C" void kernel_launch(void* const* d_in, const int* in_sizes, int n_in,
                              void* d_out, int out_size) {
    const float* coords = (const float*)d_in[0];
    const float* mask   = (const float*)d_in[1];
    const float* bonds  = (const float*)d_in[2];
    const float* pe_w   = (const float*)d_in[3];
    const float* pe_b   = (const float*)d_in[4];
    const float* edge_w = (const float*)d_in[5];
    const float* ln_g   = (const float*)d_in[6];
    const float* ln_b   = (const float*)d_in[7];
    const int*   t2c    = (const int*)d_in[8];
    const int*   resi   = (const int*)d_in[9];
    // d_in[10] = asym_id (unused: chain labels forced to zero in reference)
    const int*   lig    = (const int*)d_in[11];

    float* out    = (float*)d_out;
    float* outE   = out;                                        // B*N*K*128
    float* outIdx = out + (size_t)BB * NN * KNN * EDGE_C;       // B*N*K
    float* outD   = outIdx + (size_t)BB * NN * KNN;             // B*N*K

    gather_kernel<<<(BB * NN + 255) / 256, 256>>>(coords, mask, t2c);
    pw_kernel<<<PE_IN, EDGE_C>>>(pe_w, pe_b, edge_w);
    tokfeat_kernel<<<BB * NN, 256>>>(bonds, edge_w, ln_g, ln_b,
                                     resi, lig, outE, outIdx, outD);
}